// round 15
// baseline (speedup 1.0000x reference)
#include <cuda_runtime.h>
#include <math.h>
#include <stdint.h>

#define NN 50000
#define EE 300000
#define IN_DIM 768
#define HID 256
#define OUT_DIM 128
#define HEADS 8

#define SCAN_B 512
#define NTOT (3 * NN)
#define NBLK3 ((NTOT + SCAN_B - 1) / SCAN_B)   // 293

// pre-rounded (tf32) weight matrices, concatenated
#define BW_W0P 0
#define BW_W0A (BW_W0P + IN_DIM * HID)
#define BW_WK0 (BW_W0A + IN_DIM * HID)
#define BW_W1P (BW_WK0 + HID * HID)
#define BW_W1A (BW_W1P + HID * OUT_DIM)
#define BW_WK1 (BW_W1A + HID * OUT_DIM)
#define BW_TOTAL (BW_WK1 + OUT_DIM * OUT_DIM)   // 540672

// big-GEMM smem: A fragment-ordered [128*32] + Bs[2][32][136], dynamic
#define BS_STRIDE 136
#define ASB_ELEMS (128 * 32)                    // 4096 (fragment-ordered, no pad)
#define BSB_ELEMS (32 * BS_STRIDE)              // 4352
#define GEMM_SMEM_BIG ((ASB_ELEMS + 2 * BSB_ELEMS) * 4)   // 51200 bytes

// fragment-ordered A layout: (r, c) -> float index, c in [0,32)
//   blk  = (r>>4)*4 + (c>>3)
//   vec  = (r&7)*4 + (c&3)
//   elem = ((c>>2)&1)*2 + ((r>>3)&1)
//   idx  = blk*128 + vec*4 + elem
__device__ __forceinline__ int afrag_idx(int r, int c) {
    return (((r >> 4) * 4 + (c >> 3)) << 7) + (((r & 7) * 4 + (c & 3)) << 2)
           + (((c >> 2) & 1) * 2) + ((r >> 3) & 1);
}

// ---------------- scratch (static device globals; no allocation) ----------------
__device__ float g_H0P[NN * HID];
__device__ float g_H0A[NN * HID];
__device__ float g_SC[6][NN * HEADS];
__device__ float g_AGG0a[NN * HID];
__device__ float g_AGG0b[NN * HID];
__device__ float g_AGG0c[NN * HID];
__device__ float g_H1P[NN * OUT_DIM];
__device__ float g_H1A[NN * OUT_DIM];
__device__ float g_AGG1a[NN * OUT_DIM];
__device__ float g_AGG1b[NN * OUT_DIM];
__device__ float g_AGG1c[NN * OUT_DIM];
__device__ float g_COLSUM[2 * HID];
__device__ float g_W2[4];
__device__ float g_BW[BW_TOTAL];
// CSR (perm stores PRE-RESOLVED SOURCE NODE IDS)
__device__ int g_RP[NTOT + 8];
__device__ int g_PERM[3 * EE];
__device__ int g_CNT[NTOT];
__device__ int g_CUR[NTOT];
__device__ int g_BSUM[NBLK3 + 8];

// ---------------- common helpers ----------------
__device__ __forceinline__ uint32_t f2tf32(float x) {
    uint32_t r;
    asm("cvt.rna.tf32.f32 %0, %1;" : "=r"(r) : "f"(x));
    return r;
}

__device__ __forceinline__ void mma_tf32(float* d, const uint32_t* a, const uint32_t* b) {
    asm volatile(
        "mma.sync.aligned.m16n8k8.row.col.f32.tf32.tf32.f32 "
        "{%0,%1,%2,%3},{%4,%5,%6,%7},{%8,%9},{%0,%1,%2,%3};"
        : "+f"(d[0]), "+f"(d[1]), "+f"(d[2]), "+f"(d[3])
        : "r"(a[0]), "r"(a[1]), "r"(a[2]), "r"(a[3]), "r"(b[0]), "r"(b[1]));
}

__device__ __forceinline__ void cp16(uint32_t dst, const void* src) {
    asm volatile("cp.async.cg.shared.global [%0], [%1], 16;"
                 :: "r"(dst), "l"(src));
}
__device__ __forceinline__ void cp_commit() { asm volatile("cp.async.commit_group;"); }
template <int N_>
__device__ __forceinline__ void cp_wait() { asm volatile("cp.async.wait_group %0;" :: "n"(N_)); }

// ================= BIG GEMM: 128x128x32 CTA tile (K=768 dual L0 projection ONLY) ======
__global__ __launch_bounds__(256, 2)
void mma_gemm_big(int M, int N, int K,
                  const float* __restrict__ A_, const float* __restrict__ B_,
                  const float* __restrict__ bias_, float* __restrict__ C_,
                  const float* Ab, const float* Bb, const float* biasb, float* Cb) {
    extern __shared__ uint32_t smbuf[];
    uint32_t* As = smbuf;                                   // fragment-ordered [4096]
    uint32_t (*Bs0)[BS_STRIDE] = (uint32_t (*)[BS_STRIDE])(smbuf + ASB_ELEMS);
    uint32_t (*Bs1)[BS_STRIDE] = (uint32_t (*)[BS_STRIDE])(smbuf + ASB_ELEMS + BSB_ELEMS);

    const int tid = threadIdx.x;
    const int lane = tid & 31;
    const int warp = tid >> 5;
    const int wm = warp & 3;
    const int wn = warp >> 2;
    const int block_row = blockIdx.y * 128;
    const int block_col = blockIdx.x * 128;

    const float* A = blockIdx.z ? Ab : A_;
    const float* B = blockIdx.z ? Bb : B_;
    const float* bias = blockIdx.z ? biasb : bias_;
    float* C = blockIdx.z ? Cb : C_;

    const int arow = tid >> 3, acol = (tid & 7) * 4;
    const int brow = tid >> 5, bcol = (tid & 31) * 4;

    float acc[2][8][4];
#pragma unroll
    for (int mt = 0; mt < 2; mt++)
#pragma unroll
        for (int nt = 0; nt < 8; nt++)
#pragma unroll
            for (int r = 0; r < 4; r++) acc[mt][nt][r] = 0.f;

    float4 aReg[4];
    auto loadA = [&](int k0) {
#pragma unroll
        for (int i = 0; i < 4; i++) {
            int gr = block_row + arow + 32 * i;
            float4 v = make_float4(0.f, 0.f, 0.f, 0.f);
            if (gr < M) v = *(const float4*)(A + (size_t)gr * K + k0 + acol);
            aReg[i] = v;
        }
    };
    auto storeA = [&]() {
#pragma unroll
        for (int i = 0; i < 4; i++) {
            int r = arow + 32 * i;
            int base = afrag_idx(r, acol);   // elems at base + j*4
            As[base + 0]  = f2tf32(aReg[i].x);
            As[base + 4]  = f2tf32(aReg[i].y);
            As[base + 8]  = f2tf32(aReg[i].z);
            As[base + 12] = f2tf32(aReg[i].w);
        }
    };
    auto issueB = [&](int st, int k0) {
        uint32_t (*Bst)[BS_STRIDE] = st ? Bs1 : Bs0;
#pragma unroll
        for (int i = 0; i < 4; i++) {
            const float* src = B + (size_t)(k0 + brow + 8 * i) * N + block_col + bcol;
            uint32_t dst = (uint32_t)__cvta_generic_to_shared(&Bst[brow + 8 * i][bcol]);
            cp16(dst, src);
        }
        cp_commit();
    };

    const int numT = K / 32;
    issueB(0, 0);
    loadA(0);
    for (int t = 0; t < numT; t++) {
        storeA();
        if (t + 1 < numT) {
            issueB((t + 1) & 1, (t + 1) * 32);
            cp_wait<1>();
        } else {
            cp_wait<0>();
        }
        __syncthreads();
        if (t + 1 < numT) loadA((t + 1) * 32);
        const uint32_t (*Bsq)[BS_STRIDE] = (t & 1) ? Bs1 : Bs0;
#pragma unroll
        for (int k8 = 0; k8 < 32; k8 += 8) {
            uint32_t af[2][4], bf[8][2];
#pragma unroll
            for (int mt = 0; mt < 2; mt++) {
                int blk = (wm * 2 + mt) * 4 + (k8 >> 3);
                uint4 av = *(const uint4*)&As[blk * 128 + lane * 4];
                af[mt][0] = av.x; af[mt][1] = av.y; af[mt][2] = av.z; af[mt][3] = av.w;
            }
#pragma unroll
            for (int nt = 0; nt < 8; nt++) {
                int n = wn * 64 + nt * 8 + (lane >> 2);
                bf[nt][0] = Bsq[k8 + (lane & 3)][n];
                bf[nt][1] = Bsq[k8 + 4 + (lane & 3)][n];
            }
#pragma unroll
            for (int mt = 0; mt < 2; mt++)
#pragma unroll
                for (int nt = 0; nt < 8; nt++) mma_tf32(acc[mt][nt], af[mt], bf[nt]);
        }
        __syncthreads();
    }

#pragma unroll
    for (int mt = 0; mt < 2; mt++) {
        int r0 = block_row + wm * 32 + mt * 16 + (lane >> 2);
#pragma unroll
        for (int nt = 0; nt < 8; nt++) {
            int c0 = block_col + wn * 64 + nt * 8 + 2 * (lane & 3);
            if (r0 < M) {
                C[(size_t)r0 * N + c0]     = acc[mt][nt][0] + bias[c0];
                C[(size_t)r0 * N + c0 + 1] = acc[mt][nt][1] + bias[c0 + 1];
            }
            if (r0 + 8 < M) {
                C[(size_t)(r0 + 8) * N + c0]     = acc[mt][nt][2] + bias[c0];
                C[(size_t)(r0 + 8) * N + c0 + 1] = acc[mt][nt][3] + bias[c0 + 1];
            }
        }
    }
}

// ================= SMALL GEMM: 64x128x32 CTA tile =================
template <int MODE, int COMBINE, int DUAL>
__global__ __launch_bounds__(256)
void mma_gemm(int M, int N, int K,
              const float* __restrict__ A_, const float* __restrict__ A2,
              const float* __restrict__ B_,
              const float* __restrict__ bias_, float* __restrict__ C_,
              const float* __restrict__ wv,
              const float* Ab, const float* Bb, const float* biasb, float* Cb) {
    __shared__ uint32_t As[64 * 32];        // fragment-ordered
    __shared__ uint32_t Bs[2][32][136];

    const int tid = threadIdx.x;
    const int lane = tid & 31;
    const int warp = tid >> 5;
    const int wm = warp & 1;
    const int wn = warp >> 1;
    const int block_row = blockIdx.y * 64;
    const int block_col = blockIdx.x * 128;

    const float* A = A_;
    const float* B = B_;
    const float* bias = bias_;
    float* C = C_;
    if (DUAL && blockIdx.z) { A = Ab; B = Bb; bias = biasb; C = Cb; }
    if (MODE == 1 && blockIdx.z) A = A2;

    float w0 = 1.f, w1 = 0.f;
    if (COMBINE) { w0 = wv[0]; w1 = wv[1]; }

    const int arow = tid >> 3, acol = (tid & 7) * 4;
    const int brow = tid >> 5, bcol = (tid & 31) * 4;

    float acc[2][4][4];
#pragma unroll
    for (int mt = 0; mt < 2; mt++)
#pragma unroll
        for (int nt = 0; nt < 4; nt++)
#pragma unroll
            for (int r = 0; r < 4; r++) acc[mt][nt][r] = 0.f;

    float4 aReg[2];
    auto loadA = [&](int k0) {
#pragma unroll
        for (int i = 0; i < 2; i++) {
            int gr = block_row + arow + 32 * i;
            float4 v = make_float4(0.f, 0.f, 0.f, 0.f);
            if (gr < M) {
                v = *(const float4*)(A + (size_t)gr * K + k0 + acol);
                if (COMBINE && !(DUAL && blockIdx.z)) {
                    float4 u = *(const float4*)(A2 + (size_t)gr * K + k0 + acol);
                    v.x = w0 * v.x + w1 * u.x; v.y = w0 * v.y + w1 * u.y;
                    v.z = w0 * v.z + w1 * u.z; v.w = w0 * v.w + w1 * u.w;
                }
            }
            aReg[i] = v;
        }
    };
    auto storeA = [&]() {
#pragma unroll
        for (int i = 0; i < 2; i++) {
            int r = arow + 32 * i;
            int base = afrag_idx(r, acol);
            As[base + 0]  = f2tf32(aReg[i].x);
            As[base + 4]  = f2tf32(aReg[i].y);
            As[base + 8]  = f2tf32(aReg[i].z);
            As[base + 12] = f2tf32(aReg[i].w);
        }
    };
    auto issueB = [&](int st, int k0) {
#pragma unroll
        for (int i = 0; i < 4; i++) {
            const float* src = B + (size_t)(k0 + brow + 8 * i) * N + block_col + bcol;
            uint32_t dst = (uint32_t)__cvta_generic_to_shared(&Bs[st][brow + 8 * i][bcol]);
            cp16(dst, src);
        }
        cp_commit();
    };

    const int numT = K / 32;
    issueB(0, 0);
    loadA(0);
    for (int t = 0; t < numT; t++) {
        storeA();
        if (t + 1 < numT) {
            issueB((t + 1) & 1, (t + 1) * 32);
            cp_wait<1>();
        } else {
            cp_wait<0>();
        }
        __syncthreads();
        if (t + 1 < numT) loadA((t + 1) * 32);
        const uint32_t (*Bsq)[136] = Bs[t & 1];
#pragma unroll
        for (int k8 = 0; k8 < 32; k8 += 8) {
            uint32_t af[2][4], bf[4][2];
#pragma unroll
            for (int mt = 0; mt < 2; mt++) {
                int blk = (wm * 2 + mt) * 4 + (k8 >> 3);
                uint4 av = *(const uint4*)&As[blk * 128 + lane * 4];
                af[mt][0] = av.x; af[mt][1] = av.y; af[mt][2] = av.z; af[mt][3] = av.w;
            }
#pragma unroll
            for (int nt = 0; nt < 4; nt++) {
                int n = wn * 32 + nt * 8 + (lane >> 2);
                bf[nt][0] = Bsq[k8 + (lane & 3)][n];
                bf[nt][1] = Bsq[k8 + 4 + (lane & 3)][n];
            }
#pragma unroll
            for (int mt = 0; mt < 2; mt++)
#pragma unroll
                for (int nt = 0; nt < 4; nt++) mma_tf32(acc[mt][nt], af[mt], bf[nt]);
        }
        __syncthreads();
    }

    if (MODE == 0) {
#pragma unroll
        for (int mt = 0; mt < 2; mt++) {
            int r0 = block_row + wm * 32 + mt * 16 + (lane >> 2);
#pragma unroll
            for (int nt = 0; nt < 4; nt++) {
                int c0 = block_col + wn * 32 + nt * 8 + 2 * (lane & 3);
                if (r0 < M) {
                    C[(size_t)r0 * N + c0]     = acc[mt][nt][0] + bias[c0];
                    C[(size_t)r0 * N + c0 + 1] = acc[mt][nt][1] + bias[c0 + 1];
                }
                if (r0 + 8 < M) {
                    C[(size_t)(r0 + 8) * N + c0]     = acc[mt][nt][2] + bias[c0];
                    C[(size_t)(r0 + 8) * N + c0 + 1] = acc[mt][nt][3] + bias[c0 + 1];
                }
            }
        }
    } else {
        float* Cc = C_ + (size_t)blockIdx.z * N;
        __shared__ float csum[128];
        if (tid < 128) csum[tid] = 0.f;
        __syncthreads();
#pragma unroll
        for (int nt = 0; nt < 4; nt++) {
            int cl = wn * 32 + nt * 8 + 2 * (lane & 3);
            int cg = block_col + cl;
            float l0 = 0.f, l1 = 0.f;
#pragma unroll
            for (int mt = 0; mt < 2; mt++) {
                int r0 = block_row + wm * 32 + mt * 16 + (lane >> 2);
                if (r0 < M) {
                    l0 += tanhf(acc[mt][nt][0] + bias[cg]);
                    l1 += tanhf(acc[mt][nt][1] + bias[cg + 1]);
                }
                if (r0 + 8 < M) {
                    l0 += tanhf(acc[mt][nt][2] + bias[cg]);
                    l1 += tanhf(acc[mt][nt][3] + bias[cg + 1]);
                }
            }
            atomicAdd(&csum[cl], l0);
            atomicAdd(&csum[cl + 1], l1);
        }
        __syncthreads();
        if (tid < 128) atomicAdd(&Cc[block_col + tid], csum[tid]);
    }
}

// ---------------- CSR hist + weight pre-rounding ----------------
__global__ void hist3_preround_kernel(const int* __restrict__ e0, const int* __restrict__ e1,
                                      const int* __restrict__ e2, int* __restrict__ cnt,
                                      const float* __restrict__ w0p, const float* __restrict__ w0a,
                                      const float* __restrict__ wk0, const float* __restrict__ w1p,
                                      const float* __restrict__ w1a, const float* __restrict__ wk1,
                                      float* __restrict__ bw) {
    int i = blockIdx.x * blockDim.x + threadIdx.x;
    if (i < 3 * EE) {
        int r = i / EE, j = i - r * EE;
        const int* e = (r == 0) ? e0 : (r == 1) ? e1 : e2;
        atomicAdd(&cnt[r * NN + e[EE + j]], 1);
        return;
    }
    int k = i - 3 * EE;
    if (k >= BW_TOTAL) return;
    const float* src;
    int off;
    if (k < BW_W0A) { src = w0p; off = k - BW_W0P; }
    else if (k < BW_WK0) { src = w0a; off = k - BW_W0A; }
    else if (k < BW_W1P) { src = wk0; off = k - BW_WK0; }
    else if (k < BW_W1A) { src = w1p; off = k - BW_W1P; }
    else if (k < BW_WK1) { src = w1a; off = k - BW_W1A; }
    else { src = wk1; off = k - BW_WK1; }
    uint32_t r32 = f2tf32(src[off]);
    bw[k] = __uint_as_float(r32);
}

// ---------------- CSR scans / fill ----------------
__global__ void scanA_kernel(const int* __restrict__ cnt, int* __restrict__ rp,
                             int* __restrict__ bsum) {
    __shared__ int sh[SCAN_B];
    int t = threadIdx.x;
    int i = blockIdx.x * SCAN_B + t;
    int v = (i < NTOT) ? cnt[i] : 0;
    sh[t] = v;
    __syncthreads();
    for (int off = 1; off < SCAN_B; off <<= 1) {
        int x = (t >= off) ? sh[t - off] : 0;
        __syncthreads();
        sh[t] += x;
        __syncthreads();
    }
    if (i < NTOT) rp[i] = sh[t] - v;
    if (t == SCAN_B - 1) bsum[blockIdx.x] = sh[t];
}

__global__ void scanB_kernel(int* __restrict__ bsum, int nb) {
    __shared__ int sh[SCAN_B];
    int t = threadIdx.x;
    int v = (t < nb) ? bsum[t] : 0;
    sh[t] = v;
    __syncthreads();
    for (int off = 1; off < SCAN_B; off <<= 1) {
        int x = (t >= off) ? sh[t - off] : 0;
        __syncthreads();
        sh[t] += x;
        __syncthreads();
    }
    if (t < nb) bsum[t] = sh[t] - v;
}

__global__ void scanC_kernel(int* __restrict__ rp, const int* __restrict__ bsum,
                             int* __restrict__ cur) {
    int i = blockIdx.x * blockDim.x + threadIdx.x;
    if (i < NTOT) {
        int v = rp[i] + bsum[i / SCAN_B];
        rp[i] = v;
        cur[i] = v;
    }
    if (i == 0) rp[NTOT] = 3 * EE;
}

// stores the SOURCE NODE ID directly (gather never needs the edge id)
__global__ void fill3_kernel(const int* __restrict__ e0, const int* __restrict__ e1,
                             const int* __restrict__ e2, int* __restrict__ cur,
                             int* __restrict__ perm) {
    int i = blockIdx.x * blockDim.x + threadIdx.x;
    if (i >= 3 * EE) return;
    int r = i / EE, j = i - r * EE;
    const int* e = (r == 0) ? e0 : (r == 1) ? e1 : e2;
    int pos = atomicAdd(&cur[r * NN + e[EE + j]], 1);
    perm[pos] = e[j];
}

// ---------------- merged attention scores ----------------
template <int C, int HEADS_T>
__global__ void scores6(const float* __restrict__ HP, const float* __restrict__ HA,
                        const float* __restrict__ a0, const float* __restrict__ a1,
                        const float* __restrict__ a2, const float* __restrict__ a3,
                        const float* __restrict__ a4, const float* __restrict__ a5,
                        float* __restrict__ o0, float* __restrict__ o1,
                        float* __restrict__ o2, float* __restrict__ o3,
                        float* __restrict__ o4, float* __restrict__ o5) {
    int gw = (blockIdx.x * blockDim.x + threadIdx.x) >> 5;
    if (gw >= 2 * NN) return;
    int lane = threadIdx.x & 31;
    constexpr int EPL = C / 32;
    constexpr int G = 32 / HEADS_T;
    bool isP = (gw < NN);
    int w = isP ? gw : gw - NN;
    const float* H = isP ? HP : HA;

    float h[EPL];
    const float* row = H + (size_t)w * C + lane * EPL;
#pragma unroll
    for (int j = 0; j < EPL; j += 4) {
        float4 v = *(const float4*)(row + j);
        h[j] = v.x; h[j + 1] = v.y; h[j + 2] = v.z; h[j + 3] = v.w;
    }
    const float* av[4];
    float* ov[4];
    int nA;
    if (isP) { av[0] = a0; av[1] = a1; av[2] = a2; av[3] = a3;
               ov[0] = o0; ov[1] = o1; ov[2] = o2; ov[3] = o3; nA = 4; }
    else     { av[0] = a4; av[1] = a5; av[2] = a4; av[3] = a4;
               ov[0] = o4; ov[1] = o5; ov[2] = o4; ov[3] = o4; nA = 2; }
#pragma unroll
    for (int k = 0; k < 4; k++) {
        if (k >= nA) break;
        const float* a = av[k] + lane * EPL;
        float s = 0.f;
#pragma unroll
        for (int j = 0; j < EPL; j += 4) {
            float4 v = *(const float4*)(a + j);
            s += h[j] * v.x + h[j + 1] * v.y + h[j + 2] * v.z + h[j + 3] * v.w;
        }
#pragma unroll
        for (int off = 1; off < G; off <<= 1) s += __shfl_xor_sync(0xffffffffu, s, off);
        if ((lane & (G - 1)) == 0) ov[k][w * HEADS_T + lane / G] = s;
    }
}

// ---------------- fused softmax + CSR gather (perm = source ids) ----------------
__device__ __forceinline__ float lrelu02(float x) { return x >= 0.f ? x : 0.2f * x; }

template <int C, int HEADS_T>
__global__ void csr_gather_fused(const int* __restrict__ rp, const int* __restrict__ perm,
                                 const float* __restrict__ ss, const float* __restrict__ sd,
                                 const float* __restrict__ Hsrc, float* __restrict__ agg) {
    int w = (blockIdx.x * blockDim.x + threadIdx.x) >> 5;
    if (w >= NN) return;
    int lane = threadIdx.x & 31;
    constexpr int EPL = C / 32;
    int h = (HEADS_T == 1) ? 0 : (lane >> 2);
    float sdh = __ldg(&sd[w * HEADS_T + h]);

    float acc[EPL];
#pragma unroll
    for (int j = 0; j < EPL; j++) acc[j] = 0.f;
    float den = 0.f;

    int beg = __ldg(&rp[w]), end = __ldg(&rp[w + 1]);
    const float* base = Hsrc + (size_t)lane * EPL;
    int s0 = 0;
    if (beg < end) s0 = __ldg(&perm[beg]);
    for (int p = beg; p < end; p++) {
        int s = s0;
        if (p + 1 < end) s0 = __ldg(&perm[p + 1]);
        float al = lrelu02(__ldg(&ss[s * HEADS_T + h]) + sdh);
        float ex = __expf(fminf(al, 80.f));
        den += ex;
        const float* src = base + (size_t)s * C;
#pragma unroll
        for (int j = 0; j < EPL; j += 4) {
            float4 v = *(const float4*)(src + j);
            acc[j]     += ex * v.x;
            acc[j + 1] += ex * v.y;
            acc[j + 2] += ex * v.z;
            acc[j + 3] += ex * v.w;
        }
    }
    float inv = 1.f / (den + 1e-16f);
    float* dst = agg + (size_t)w * C + lane * EPL;
#pragma unroll
    for (int j = 0; j < EPL; j += 4) {
        float4 v;
        v.x = fmaxf(acc[j] * inv, 0.f);
        v.y = fmaxf(acc[j + 1] * inv, 0.f);
        v.z = fmaxf(acc[j + 2] * inv, 0.f);
        v.w = fmaxf(acc[j + 3] * inv, 0.f);
        *(float4*)(dst + j) = v;
    }
}

// ---------------- small kernels ----------------
__global__ void semantic_weights_kernel(const float* __restrict__ colsum,
                                        const float* __restrict__ q,
                                        int C, float invn, float* __restrict__ w) {
    __shared__ float sh0[256], sh1[256];
    int t = threadIdx.x;
    float s0 = 0.f, s1 = 0.f;
    for (int c = t; c < C; c += blockDim.x) {
        float qc = q[c];
        s0 += qc * colsum[c];
        s1 += qc * colsum[C + c];
    }
    sh0[t] = s0; sh1[t] = s1;
    __syncthreads();
    for (int o = blockDim.x / 2; o > 0; o >>= 1) {
        if (t < o) { sh0[t] += sh0[t + o]; sh1[t] += sh1[t + o]; }
        __syncthreads();
    }
    if (t == 0) {
        float a = sh0[0] * invn, b = sh1[0] * invn;
        float m = fmaxf(a, b);
        float ea = expf(a - m), eb = expf(b - m);
        float inv = 1.f / (ea + eb);
        w[0] = ea * inv; w[1] = eb * inv;
    }
}

// merged output: warps [0,NN) -> paper = l2n(w0*A + w1*B); [NN,2NN) -> author = l2n(Cc)
__global__ void l2norm_final_kernel(const float* __restrict__ A, const float* __restrict__ B,
                                    const float* __restrict__ Cc,
                                    const float* __restrict__ w, float* __restrict__ out) {
    int gw = (blockIdx.x * blockDim.x + threadIdx.x) >> 5;
    if (gw >= 2 * NN) return;
    int lane = threadIdx.x & 31;
    float4 v;
    if (gw < NN) {
        float w0 = w[0], w1 = w[1];
        float4 a = *(const float4*)(A + (size_t)gw * 128 + lane * 4);
        float4 b = *(const float4*)(B + (size_t)gw * 128 + lane * 4);
        v.x = w0 * a.x + w1 * b.x;
        v.y = w0 * a.y + w1 * b.y;
        v.z = w0 * a.z + w1 * b.z;
        v.w = w0 * a.w + w1 * b.w;
    } else {
        v = *(const float4*)(Cc + (size_t)(gw - NN) * 128 + lane * 4);
    }
    float s = v.x * v.x + v.y * v.y + v.z * v.z + v.w * v.w;
#pragma unroll
    for (int off = 16; off > 0; off >>= 1) s += __shfl_xor_sync(0xffffffffu, s, off);
    float inv = 1.f / fmaxf(sqrtf(s), 1e-12f);
    v.x *= inv; v.y *= inv; v.z *= inv; v.w *= inv;
    *(float4*)(out + (size_t)gw * 128 + lane * 4) = v;
}

// ---------------- host orchestration ----------------
enum {
    L_XP, L_XA, L_W0P, L_B0P, L_W0A, L_B0A,
    L_A0S_W, L_A0D_W, L_A0S_WB, L_A0D_WB, L_A0S_C, L_A0D_C,
    L_WK0, L_BK0, L_Q0,
    L_W1P, L_B1P, L_W1A, L_B1A,
    L_A1S_W, L_A1D_W, L_A1S_WB, L_A1D_WB, L_A1S_C, L_A1D_C,
    L_WK1, L_BK1, L_Q1, L_EIW, L_EIWB, L_EIC, L_COUNT
};

extern "C" void kernel_launch(void* const* d_in, const int* in_sizes, int n_in,
                              void* d_out, int out_size) {
    static const int mapSig[L_COUNT] = {
        0, 1, 2, 3, 4, 5, 6, 7, 8, 9, 10, 11, 12, 13, 14,
        15, 16, 17, 18, 19, 20, 21, 22, 23, 24, 25, 26, 27, 28, 29, 30};
    static const int mapDict[L_COUNT] = {
        0, 1, 5, 6, 7, 8, 9, 10, 11, 12, 13, 14, 15, 16, 17,
        18, 19, 20, 21, 22, 23, 24, 25, 26, 27, 28, 29, 30, 2, 3, 4};
    const int* mp = (n_in > 2 && in_sizes[2] == 2 * EE) ? mapDict : mapSig;

    const float* in_f[L_COUNT];
    for (int i = 0; i < L_COUNT; i++) in_f[i] = (const float*)d_in[mp[i]];
    const int* ei[3] = {(const int*)d_in[mp[L_EIW]],
                        (const int*)d_in[mp[L_EIWB]],
                        (const int*)d_in[mp[L_EIC]]};

    float *H0P, *H0A, *SC;
    float *AGG0a, *AGG0b, *AGG0c;
    float *H1P, *H1A, *AGG1a, *AGG1b, *AGG1c, *COLSUM, *W2, *BW;
    int *RP, *PERM, *CNT, *CUR, *BSUM;
    cudaGetSymbolAddress((void**)&H0P, g_H0P);
    cudaGetSymbolAddress((void**)&H0A, g_H0A);
    cudaGetSymbolAddress((void**)&SC, g_SC);
    cudaGetSymbolAddress((void**)&AGG0a, g_AGG0a);
    cudaGetSymbolAddress((void**)&AGG0b, g_AGG0b);
    cudaGetSymbolAddress((void**)&AGG0c, g_AGG0c);
    cudaGetSymbolAddress((void**)&H1P, g_H1P);
    cudaGetSymbolAddress((void**)&H1A, g_H1A);
    cudaGetSymbolAddress((void**)&AGG1a, g_AGG1a);
    cudaGetSymbolAddress((void**)&AGG1b, g_AGG1b);
    cudaGetSymbolAddress((void**)&AGG1c, g_AGG1c);
    cudaGetSymbolAddress((void**)&COLSUM, g_COLSUM);
    cudaGetSymbolAddress((void**)&W2, g_W2);
    cudaGetSymbolAddress((void**)&BW, g_BW);
    cudaGetSymbolAddress((void**)&RP, g_RP);
    cudaGetSymbolAddress((void**)&PERM, g_PERM);
    cudaGetSymbolAddress((void**)&CNT, g_CNT);
    cudaGetSymbolAddress((void**)&CUR, g_CUR);
    cudaGetSymbolAddress((void**)&BSUM, g_BSUM);

    float* S0 = SC + 0 * (NN * HEADS);
    float* S1 = SC + 1 * (NN * HEADS);
    float* S2 = SC + 2 * (NN * HEADS);
    float* S3 = SC + 3 * (NN * HEADS);
    float* S4 = SC + 4 * (NN * HEADS);
    float* S5 = SC + 5 * (NN * HEADS);
    float* W2a = W2;
    float* W2b = W2 + 2;
    const float* BW0P = BW + BW_W0P;
    const float* BW0A = BW + BW_W0A;
    const float* BWK0 = BW + BW_WK0;
    const float* BW1P = BW + BW_W1P;
    const float* BW1A = BW + BW_W1A;
    const float* BWK1 = BW + BW_WK1;

    cudaFuncSetAttribute(mma_gemm_big, cudaFuncAttributeMaxDynamicSharedMemorySize, GEMM_SMEM_BIG);

    const int TPB = 256;
    const int GY128 = (NN + 127) / 128;
    const int GY64 = (NN + 63) / 64;
    dim3 gProj0(2, GY128, 2);
    dim3 gProj1(1, GY64, 2);
    dim3 gCol256(2, GY64, 2);
    dim3 gCol128(1, GY64, 2);
    int warpBlocks = (NN * 32 + TPB - 1) / TPB;
    int scores6Blocks = (2 * NN + 7) / 8;

    // ======== CSR prefix (+weight preround) + L0 projections ========
    cudaMemsetAsync(CNT, 0, NTOT * sizeof(int));
    hist3_preround_kernel<<<(3 * EE + BW_TOTAL + TPB - 1) / TPB, TPB>>>(
        ei[0], ei[1], ei[2], CNT,
        in_f[L_W0P], in_f[L_W0A], in_f[L_WK0], in_f[L_W1P], in_f[L_W1A], in_f[L_WK1], BW);
    scanA_kernel<<<NBLK3, SCAN_B>>>(CNT, RP, BSUM);
    scanB_kernel<<<1, SCAN_B>>>(BSUM, NBLK3);
    mma_gemm_big<<<gProj0, TPB, GEMM_SMEM_BIG>>>(NN, HID, IN_DIM,
        in_f[L_XP], BW0P, in_f[L_B0P], H0P,
        in_f[L_XA], BW0A, in_f[L_B0A], H0A);
    scanC_kernel<<<(NTOT + TPB - 1) / TPB, TPB>>>(RP, BSUM, CUR);
    fill3_kernel<<<(3 * EE + TPB - 1) / TPB, TPB>>>(ei[0], ei[1], ei[2], CUR, PERM);

    // ======== Layer 0 ========
    scores6<HID, HEADS><<<scores6Blocks, TPB>>>(H0P, H0A,
        in_f[L_A0D_W], in_f[L_A0S_WB], in_f[L_A0S_C], in_f[L_A0D_C],
        in_f[L_A0S_W], in_f[L_A0D_WB],
        S1, S2, S4, S5, S0, S3);

    csr_gather_fused<HID, HEADS><<<warpBlocks, TPB>>>(RP + 0 * NN, PERM, S0, S1, H0A, AGG0a);
    csr_gather_fused<HID, HEADS><<<warpBlocks, TPB>>>(RP + 1 * NN, PERM, S2, S3, H0P, AGG0b);
    csr_gather_fused<HID, HEADS><<<warpBlocks, TPB>>>(RP + 2 * NN, PERM, S4, S5, H0P, AGG0c);

    cudaMemsetAsync(COLSUM, 0, 2 * HID * sizeof(float));
    mma_gemm<1, 0, 0><<<gCol256, TPB>>>(NN, HID, HID,
        AGG0a, AGG0c, BWK0, in_f[L_BK0], COLSUM, nullptr,
        nullptr, nullptr, nullptr, nullptr);
    semantic_weights_kernel<<<1, 256>>>(COLSUM, in_f[L_Q0], HID, 1.f / NN, W2a);

    // ======== Layer 1 ========
    mma_gemm<0, 1, 1><<<gProj1, TPB>>>(NN, OUT_DIM, HID,
        AGG0a, AGG0c, BW1P, in_f[L_B1P], H1P, W2a,
        AGG0b, BW1A, in_f[L_B1A], H1A);

    scores6<OUT_DIM, 1><<<scores6Blocks, TPB>>>(H1P, H1A,
        in_f[L_A1D_W], in_f[L_A1S_WB], in_f[L_A1S_C], in_f[L_A1D_C],
        in_f[L_A1S_W], in_f[L_A1D_WB],
        S1, S2, S4, S5, S0, S3);

    csr_gather_fused<OUT_DIM, 1><<<warpBlocks, TPB>>>(RP + 0 * NN, PERM, S0, S1, H1A, AGG1a);
    csr_gather_fused<OUT_DIM, 1><<<warpBlocks, TPB>>>(RP + 1 * NN, PERM, S2, S3, H1P, AGG1b);
    csr_gather_fused<OUT_DIM, 1><<<warpBlocks, TPB>>>(RP + 2 * NN, PERM, S4, S5, H1P, AGG1c);

    cudaMemsetAsync(COLSUM, 0, 2 * OUT_DIM * sizeof(float));
    mma_gemm<1, 0, 0><<<gCol128, TPB>>>(NN, OUT_DIM, OUT_DIM,
        AGG1a, AGG1c, BWK1, in_f[L_BK1], COLSUM, nullptr,
        nullptr, nullptr, nullptr, nullptr);
    semantic_weights_kernel<<<1, 256>>>(COLSUM, in_f[L_Q1], OUT_DIM, 1.f / NN, W2b);

    // ======== merged output epilogue ========
    l2norm_final_kernel<<<(2 * NN + 7) / 8, TPB>>>(AGG1a, AGG1c, AGG1b, W2b, (float*)d_out);
}

// round 16
// speedup vs baseline: 1.1815x; 1.1815x over previous
#include <cuda_runtime.h>
#include <math.h>
#include <stdint.h>

#define NN 50000
#define EE 300000
#define IN_DIM 768
#define HID 256
#define OUT_DIM 128
#define HEADS 8

#define SCAN_B 512
#define NTOT (3 * NN)
#define NBLK3 ((NTOT + SCAN_B - 1) / SCAN_B)   // 293

// pre-rounded (tf32) weight matrices, concatenated
#define BW_W0P 0
#define BW_W0A (BW_W0P + IN_DIM * HID)
#define BW_WK0 (BW_W0A + IN_DIM * HID)
#define BW_W1P (BW_WK0 + HID * HID)
#define BW_W1A (BW_W1P + HID * OUT_DIM)
#define BW_WK1 (BW_W1A + HID * OUT_DIM)
#define BW_TOTAL (BW_WK1 + OUT_DIM * OUT_DIM)   // 540672

// big-GEMM smem: As[128][36] + Bs[2][32][136], dynamic
#define AS_STRIDE 36
#define BS_STRIDE 136
#define ASB_ELEMS (128 * AS_STRIDE)             // 4608
#define BSB_ELEMS (32 * BS_STRIDE)              // 4352
#define GEMM_SMEM_BIG ((ASB_ELEMS + 2 * BSB_ELEMS) * 4)   // 53248 bytes

// ---------------- scratch (static device globals; no allocation) ----------------
__device__ float g_H0P[NN * HID];
__device__ float g_H0A[NN * HID];
__device__ float g_SC[6][NN * HEADS];
__device__ float g_AGG0a[NN * HID];
__device__ float g_AGG0b[NN * HID];
__device__ float g_AGG0c[NN * HID];
__device__ float g_H1P[NN * OUT_DIM];
__device__ float g_H1A[NN * OUT_DIM];
__device__ float g_AGG1a[NN * OUT_DIM];
__device__ float g_AGG1b[NN * OUT_DIM];
__device__ float g_AGG1c[NN * OUT_DIM];
__device__ float g_COLSUM[2 * HID];
__device__ float g_W2[4];
__device__ float g_BW[BW_TOTAL];
// CSR (perm stores PRE-RESOLVED SOURCE NODE IDS)
__device__ int g_RP[NTOT + 8];
__device__ int g_PERM[3 * EE];
__device__ int g_CNT[NTOT];
__device__ int g_CUR[NTOT];
__device__ int g_BSUM[NBLK3 + 8];

// ---------------- common helpers ----------------
__device__ __forceinline__ uint32_t f2tf32(float x) {
    uint32_t r;
    asm("cvt.rna.tf32.f32 %0, %1;" : "=r"(r) : "f"(x));
    return r;
}

__device__ __forceinline__ void mma_tf32(float* d, const uint32_t* a, const uint32_t* b) {
    asm volatile(
        "mma.sync.aligned.m16n8k8.row.col.f32.tf32.tf32.f32 "
        "{%0,%1,%2,%3},{%4,%5,%6,%7},{%8,%9},{%0,%1,%2,%3};"
        : "+f"(d[0]), "+f"(d[1]), "+f"(d[2]), "+f"(d[3])
        : "r"(a[0]), "r"(a[1]), "r"(a[2]), "r"(a[3]), "r"(b[0]), "r"(b[1]));
}

__device__ __forceinline__ void cp16(uint32_t dst, const void* src) {
    asm volatile("cp.async.cg.shared.global [%0], [%1], 16;"
                 :: "r"(dst), "l"(src));
}
__device__ __forceinline__ void cp_commit() { asm volatile("cp.async.commit_group;"); }
template <int N_>
__device__ __forceinline__ void cp_wait() { asm volatile("cp.async.wait_group %0;" :: "n"(N_)); }

// ================= BIG GEMM: 128x128x32 CTA tile (K=768 dual L0 projection ONLY) ======
__global__ __launch_bounds__(256, 2)
void mma_gemm_big(int M, int N, int K,
                  const float* __restrict__ A_, const float* __restrict__ B_,
                  const float* __restrict__ bias_, float* __restrict__ C_,
                  const float* Ab, const float* Bb, const float* biasb, float* Cb) {
    extern __shared__ uint32_t smbuf[];
    uint32_t (*As)[AS_STRIDE] = (uint32_t (*)[AS_STRIDE])smbuf;
    uint32_t (*Bs0)[BS_STRIDE] = (uint32_t (*)[BS_STRIDE])(smbuf + ASB_ELEMS);
    uint32_t (*Bs1)[BS_STRIDE] = (uint32_t (*)[BS_STRIDE])(smbuf + ASB_ELEMS + BSB_ELEMS);

    const int tid = threadIdx.x;
    const int lane = tid & 31;
    const int warp = tid >> 5;
    const int wm = warp & 3;
    const int wn = warp >> 2;
    const int block_row = blockIdx.y * 128;
    const int block_col = blockIdx.x * 128;

    const float* A = blockIdx.z ? Ab : A_;
    const float* B = blockIdx.z ? Bb : B_;
    const float* bias = blockIdx.z ? biasb : bias_;
    float* C = blockIdx.z ? Cb : C_;

    const int arow = tid >> 3, acol = (tid & 7) * 4;
    const int brow = tid >> 5, bcol = (tid & 31) * 4;

    float acc[2][8][4];
#pragma unroll
    for (int mt = 0; mt < 2; mt++)
#pragma unroll
        for (int nt = 0; nt < 8; nt++)
#pragma unroll
            for (int r = 0; r < 4; r++) acc[mt][nt][r] = 0.f;

    float4 aReg[4];
    auto loadA = [&](int k0) {
#pragma unroll
        for (int i = 0; i < 4; i++) {
            int gr = block_row + arow + 32 * i;
            float4 v = make_float4(0.f, 0.f, 0.f, 0.f);
            if (gr < M) v = *(const float4*)(A + (size_t)gr * K + k0 + acol);
            aReg[i] = v;
        }
    };
    auto storeA = [&]() {
#pragma unroll
        for (int i = 0; i < 4; i++) {
            int r = arow + 32 * i;
            As[r][acol + 0] = f2tf32(aReg[i].x); As[r][acol + 1] = f2tf32(aReg[i].y);
            As[r][acol + 2] = f2tf32(aReg[i].z); As[r][acol + 3] = f2tf32(aReg[i].w);
        }
    };
    auto issueB = [&](int st, int k0) {
        uint32_t (*Bst)[BS_STRIDE] = st ? Bs1 : Bs0;
#pragma unroll
        for (int i = 0; i < 4; i++) {
            const float* src = B + (size_t)(k0 + brow + 8 * i) * N + block_col + bcol;
            uint32_t dst = (uint32_t)__cvta_generic_to_shared(&Bst[brow + 8 * i][bcol]);
            cp16(dst, src);
        }
        cp_commit();
    };

    const int numT = K / 32;
    issueB(0, 0);
    loadA(0);
    for (int t = 0; t < numT; t++) {
        storeA();
        if (t + 1 < numT) {
            issueB((t + 1) & 1, (t + 1) * 32);
            cp_wait<1>();
        } else {
            cp_wait<0>();
        }
        __syncthreads();
        if (t + 1 < numT) loadA((t + 1) * 32);
        const uint32_t (*Bsq)[BS_STRIDE] = (t & 1) ? Bs1 : Bs0;
#pragma unroll
        for (int k8 = 0; k8 < 32; k8 += 8) {
            uint32_t af[2][4], bf[8][2];
#pragma unroll
            for (int mt = 0; mt < 2; mt++) {
                int r0 = wm * 32 + mt * 16 + (lane >> 2);
                int c0 = k8 + (lane & 3);
                af[mt][0] = As[r0][c0];
                af[mt][1] = As[r0 + 8][c0];
                af[mt][2] = As[r0][c0 + 4];
                af[mt][3] = As[r0 + 8][c0 + 4];
            }
#pragma unroll
            for (int nt = 0; nt < 8; nt++) {
                int n = wn * 64 + nt * 8 + (lane >> 2);
                bf[nt][0] = Bsq[k8 + (lane & 3)][n];
                bf[nt][1] = Bsq[k8 + 4 + (lane & 3)][n];
            }
#pragma unroll
            for (int mt = 0; mt < 2; mt++)
#pragma unroll
                for (int nt = 0; nt < 8; nt++) mma_tf32(acc[mt][nt], af[mt], bf[nt]);
        }
        __syncthreads();
    }

#pragma unroll
    for (int mt = 0; mt < 2; mt++) {
        int r0 = block_row + wm * 32 + mt * 16 + (lane >> 2);
#pragma unroll
        for (int nt = 0; nt < 8; nt++) {
            int c0 = block_col + wn * 64 + nt * 8 + 2 * (lane & 3);
            if (r0 < M) {
                C[(size_t)r0 * N + c0]     = acc[mt][nt][0] + bias[c0];
                C[(size_t)r0 * N + c0 + 1] = acc[mt][nt][1] + bias[c0 + 1];
            }
            if (r0 + 8 < M) {
                C[(size_t)(r0 + 8) * N + c0]     = acc[mt][nt][2] + bias[c0];
                C[(size_t)(r0 + 8) * N + c0 + 1] = acc[mt][nt][3] + bias[c0 + 1];
            }
        }
    }
}

// ================= SMALL GEMM: 64x128x32 CTA tile =================
template <int MODE, int COMBINE, int DUAL>
__global__ __launch_bounds__(256)
void mma_gemm(int M, int N, int K,
              const float* __restrict__ A_, const float* __restrict__ A2,
              const float* __restrict__ B_,
              const float* __restrict__ bias_, float* __restrict__ C_,
              const float* __restrict__ wv,
              const float* Ab, const float* Bb, const float* biasb, float* Cb) {
    __shared__ uint32_t As[64][36];
    __shared__ uint32_t Bs[2][32][136];

    const int tid = threadIdx.x;
    const int lane = tid & 31;
    const int warp = tid >> 5;
    const int wm = warp & 1;
    const int wn = warp >> 1;
    const int block_row = blockIdx.y * 64;
    const int block_col = blockIdx.x * 128;

    const float* A = A_;
    const float* B = B_;
    const float* bias = bias_;
    float* C = C_;
    if (DUAL && blockIdx.z) { A = Ab; B = Bb; bias = biasb; C = Cb; }
    if (MODE == 1 && blockIdx.z) A = A2;

    float w0 = 1.f, w1 = 0.f;
    if (COMBINE) { w0 = wv[0]; w1 = wv[1]; }

    const int arow = tid >> 3, acol = (tid & 7) * 4;
    const int brow = tid >> 5, bcol = (tid & 31) * 4;

    float acc[2][4][4];
#pragma unroll
    for (int mt = 0; mt < 2; mt++)
#pragma unroll
        for (int nt = 0; nt < 4; nt++)
#pragma unroll
            for (int r = 0; r < 4; r++) acc[mt][nt][r] = 0.f;

    float4 aReg[2];
    auto loadA = [&](int k0) {
#pragma unroll
        for (int i = 0; i < 2; i++) {
            int gr = block_row + arow + 32 * i;
            float4 v = make_float4(0.f, 0.f, 0.f, 0.f);
            if (gr < M) {
                v = *(const float4*)(A + (size_t)gr * K + k0 + acol);
                if (COMBINE && !(DUAL && blockIdx.z)) {
                    float4 u = *(const float4*)(A2 + (size_t)gr * K + k0 + acol);
                    v.x = w0 * v.x + w1 * u.x; v.y = w0 * v.y + w1 * u.y;
                    v.z = w0 * v.z + w1 * u.z; v.w = w0 * v.w + w1 * u.w;
                }
            }
            aReg[i] = v;
        }
    };
    auto storeA = [&]() {
#pragma unroll
        for (int i = 0; i < 2; i++) {
            int r = arow + 32 * i;
            As[r][acol + 0] = f2tf32(aReg[i].x); As[r][acol + 1] = f2tf32(aReg[i].y);
            As[r][acol + 2] = f2tf32(aReg[i].z); As[r][acol + 3] = f2tf32(aReg[i].w);
        }
    };
    auto issueB = [&](int st, int k0) {
#pragma unroll
        for (int i = 0; i < 4; i++) {
            const float* src = B + (size_t)(k0 + brow + 8 * i) * N + block_col + bcol;
            uint32_t dst = (uint32_t)__cvta_generic_to_shared(&Bs[st][brow + 8 * i][bcol]);
            cp16(dst, src);
        }
        cp_commit();
    };

    const int numT = K / 32;
    issueB(0, 0);
    loadA(0);
    for (int t = 0; t < numT; t++) {
        storeA();
        if (t + 1 < numT) {
            issueB((t + 1) & 1, (t + 1) * 32);
            cp_wait<1>();
        } else {
            cp_wait<0>();
        }
        __syncthreads();
        if (t + 1 < numT) loadA((t + 1) * 32);
        const uint32_t (*Bsq)[136] = Bs[t & 1];
#pragma unroll
        for (int k8 = 0; k8 < 32; k8 += 8) {
            uint32_t af[2][4], bf[4][2];
#pragma unroll
            for (int mt = 0; mt < 2; mt++) {
                int r0 = wm * 32 + mt * 16 + (lane >> 2);
                int c0 = k8 + (lane & 3);
                af[mt][0] = As[r0][c0];
                af[mt][1] = As[r0 + 8][c0];
                af[mt][2] = As[r0][c0 + 4];
                af[mt][3] = As[r0 + 8][c0 + 4];
            }
#pragma unroll
            for (int nt = 0; nt < 4; nt++) {
                int n = wn * 32 + nt * 8 + (lane >> 2);
                bf[nt][0] = Bsq[k8 + (lane & 3)][n];
                bf[nt][1] = Bsq[k8 + 4 + (lane & 3)][n];
            }
#pragma unroll
            for (int mt = 0; mt < 2; mt++)
#pragma unroll
                for (int nt = 0; nt < 4; nt++) mma_tf32(acc[mt][nt], af[mt], bf[nt]);
        }
        __syncthreads();
    }

    if (MODE == 0) {
#pragma unroll
        for (int mt = 0; mt < 2; mt++) {
            int r0 = block_row + wm * 32 + mt * 16 + (lane >> 2);
#pragma unroll
            for (int nt = 0; nt < 4; nt++) {
                int c0 = block_col + wn * 32 + nt * 8 + 2 * (lane & 3);
                if (r0 < M) {
                    C[(size_t)r0 * N + c0]     = acc[mt][nt][0] + bias[c0];
                    C[(size_t)r0 * N + c0 + 1] = acc[mt][nt][1] + bias[c0 + 1];
                }
                if (r0 + 8 < M) {
                    C[(size_t)(r0 + 8) * N + c0]     = acc[mt][nt][2] + bias[c0];
                    C[(size_t)(r0 + 8) * N + c0 + 1] = acc[mt][nt][3] + bias[c0 + 1];
                }
            }
        }
    } else {
        float* Cc = C_ + (size_t)blockIdx.z * N;
        __shared__ float csum[128];
        if (tid < 128) csum[tid] = 0.f;
        __syncthreads();
#pragma unroll
        for (int nt = 0; nt < 4; nt++) {
            int cl = wn * 32 + nt * 8 + 2 * (lane & 3);
            int cg = block_col + cl;
            float l0 = 0.f, l1 = 0.f;
#pragma unroll
            for (int mt = 0; mt < 2; mt++) {
                int r0 = block_row + wm * 32 + mt * 16 + (lane >> 2);
                if (r0 < M) {
                    l0 += tanhf(acc[mt][nt][0] + bias[cg]);
                    l1 += tanhf(acc[mt][nt][1] + bias[cg + 1]);
                }
                if (r0 + 8 < M) {
                    l0 += tanhf(acc[mt][nt][2] + bias[cg]);
                    l1 += tanhf(acc[mt][nt][3] + bias[cg + 1]);
                }
            }
            atomicAdd(&csum[cl], l0);
            atomicAdd(&csum[cl + 1], l1);
        }
        __syncthreads();
        if (tid < 128) atomicAdd(&Cc[block_col + tid], csum[tid]);
    }
}

// ---------------- CSR hist + weight pre-rounding ----------------
__global__ void hist3_preround_kernel(const int* __restrict__ e0, const int* __restrict__ e1,
                                      const int* __restrict__ e2, int* __restrict__ cnt,
                                      const float* __restrict__ w0p, const float* __restrict__ w0a,
                                      const float* __restrict__ wk0, const float* __restrict__ w1p,
                                      const float* __restrict__ w1a, const float* __restrict__ wk1,
                                      float* __restrict__ bw) {
    int i = blockIdx.x * blockDim.x + threadIdx.x;
    if (i < 3 * EE) {
        int r = i / EE, j = i - r * EE;
        const int* e = (r == 0) ? e0 : (r == 1) ? e1 : e2;
        atomicAdd(&cnt[r * NN + e[EE + j]], 1);
        return;
    }
    int k = i - 3 * EE;
    if (k >= BW_TOTAL) return;
    const float* src;
    int off;
    if (k < BW_W0A) { src = w0p; off = k - BW_W0P; }
    else if (k < BW_WK0) { src = w0a; off = k - BW_W0A; }
    else if (k < BW_W1P) { src = wk0; off = k - BW_WK0; }
    else if (k < BW_W1A) { src = w1p; off = k - BW_W1P; }
    else if (k < BW_WK1) { src = w1a; off = k - BW_W1A; }
    else { src = wk1; off = k - BW_WK1; }
    uint32_t r32 = f2tf32(src[off]);
    bw[k] = __uint_as_float(r32);
}

// ---------------- CSR scans / fill ----------------
__global__ void scanA_kernel(const int* __restrict__ cnt, int* __restrict__ rp,
                             int* __restrict__ bsum) {
    __shared__ int sh[SCAN_B];
    int t = threadIdx.x;
    int i = blockIdx.x * SCAN_B + t;
    int v = (i < NTOT) ? cnt[i] : 0;
    sh[t] = v;
    __syncthreads();
    for (int off = 1; off < SCAN_B; off <<= 1) {
        int x = (t >= off) ? sh[t - off] : 0;
        __syncthreads();
        sh[t] += x;
        __syncthreads();
    }
    if (i < NTOT) rp[i] = sh[t] - v;
    if (t == SCAN_B - 1) bsum[blockIdx.x] = sh[t];
}

__global__ void scanB_kernel(int* __restrict__ bsum, int nb) {
    __shared__ int sh[SCAN_B];
    int t = threadIdx.x;
    int v = (t < nb) ? bsum[t] : 0;
    sh[t] = v;
    __syncthreads();
    for (int off = 1; off < SCAN_B; off <<= 1) {
        int x = (t >= off) ? sh[t - off] : 0;
        __syncthreads();
        sh[t] += x;
        __syncthreads();
    }
    if (t < nb) bsum[t] = sh[t] - v;
}

__global__ void scanC_kernel(int* __restrict__ rp, const int* __restrict__ bsum,
                             int* __restrict__ cur) {
    int i = blockIdx.x * blockDim.x + threadIdx.x;
    if (i < NTOT) {
        int v = rp[i] + bsum[i / SCAN_B];
        rp[i] = v;
        cur[i] = v;
    }
    if (i == 0) rp[NTOT] = 3 * EE;
}

// stores the SOURCE NODE ID directly (gather never needs the edge id)
__global__ void fill3_kernel(const int* __restrict__ e0, const int* __restrict__ e1,
                             const int* __restrict__ e2, int* __restrict__ cur,
                             int* __restrict__ perm) {
    int i = blockIdx.x * blockDim.x + threadIdx.x;
    if (i >= 3 * EE) return;
    int r = i / EE, j = i - r * EE;
    const int* e = (r == 0) ? e0 : (r == 1) ? e1 : e2;
    int pos = atomicAdd(&cur[r * NN + e[EE + j]], 1);
    perm[pos] = e[j];
}

// ---------------- merged attention scores ----------------
template <int C, int HEADS_T>
__global__ void scores6(const float* __restrict__ HP, const float* __restrict__ HA,
                        const float* __restrict__ a0, const float* __restrict__ a1,
                        const float* __restrict__ a2, const float* __restrict__ a3,
                        const float* __restrict__ a4, const float* __restrict__ a5,
                        float* __restrict__ o0, float* __restrict__ o1,
                        float* __restrict__ o2, float* __restrict__ o3,
                        float* __restrict__ o4, float* __restrict__ o5) {
    int gw = (blockIdx.x * blockDim.x + threadIdx.x) >> 5;
    if (gw >= 2 * NN) return;
    int lane = threadIdx.x & 31;
    constexpr int EPL = C / 32;
    constexpr int G = 32 / HEADS_T;
    bool isP = (gw < NN);
    int w = isP ? gw : gw - NN;
    const float* H = isP ? HP : HA;

    float h[EPL];
    const float* row = H + (size_t)w * C + lane * EPL;
#pragma unroll
    for (int j = 0; j < EPL; j += 4) {
        float4 v = *(const float4*)(row + j);
        h[j] = v.x; h[j + 1] = v.y; h[j + 2] = v.z; h[j + 3] = v.w;
    }
    const float* av[4];
    float* ov[4];
    int nA;
    if (isP) { av[0] = a0; av[1] = a1; av[2] = a2; av[3] = a3;
               ov[0] = o0; ov[1] = o1; ov[2] = o2; ov[3] = o3; nA = 4; }
    else     { av[0] = a4; av[1] = a5; av[2] = a4; av[3] = a4;
               ov[0] = o4; ov[1] = o5; ov[2] = o4; ov[3] = o4; nA = 2; }
#pragma unroll
    for (int k = 0; k < 4; k++) {
        if (k >= nA) break;
        const float* a = av[k] + lane * EPL;
        float s = 0.f;
#pragma unroll
        for (int j = 0; j < EPL; j += 4) {
            float4 v = *(const float4*)(a + j);
            s += h[j] * v.x + h[j + 1] * v.y + h[j + 2] * v.z + h[j + 3] * v.w;
        }
#pragma unroll
        for (int off = 1; off < G; off <<= 1) s += __shfl_xor_sync(0xffffffffu, s, off);
        if ((lane & (G - 1)) == 0) ov[k][w * HEADS_T + lane / G] = s;
    }
}

// ---------------- fused softmax + CSR gather (perm = source ids) ----------------
__device__ __forceinline__ float lrelu02(float x) { return x >= 0.f ? x : 0.2f * x; }

template <int C, int HEADS_T>
__global__ void csr_gather_fused(const int* __restrict__ rp, const int* __restrict__ perm,
                                 const float* __restrict__ ss, const float* __restrict__ sd,
                                 const float* __restrict__ Hsrc, float* __restrict__ agg) {
    int w = (blockIdx.x * blockDim.x + threadIdx.x) >> 5;
    if (w >= NN) return;
    int lane = threadIdx.x & 31;
    constexpr int EPL = C / 32;
    int h = (HEADS_T == 1) ? 0 : (lane >> 2);
    float sdh = __ldg(&sd[w * HEADS_T + h]);

    float acc[EPL];
#pragma unroll
    for (int j = 0; j < EPL; j++) acc[j] = 0.f;
    float den = 0.f;

    int beg = __ldg(&rp[w]), end = __ldg(&rp[w + 1]);
    const float* base = Hsrc + (size_t)lane * EPL;
    int s0 = 0;
    if (beg < end) s0 = __ldg(&perm[beg]);
    for (int p = beg; p < end; p++) {
        int s = s0;
        if (p + 1 < end) s0 = __ldg(&perm[p + 1]);
        float al = lrelu02(__ldg(&ss[s * HEADS_T + h]) + sdh);
        float ex = __expf(fminf(al, 80.f));
        den += ex;
        const float* src = base + (size_t)s * C;
#pragma unroll
        for (int j = 0; j < EPL; j += 4) {
            float4 v = *(const float4*)(src + j);
            acc[j]     += ex * v.x;
            acc[j + 1] += ex * v.y;
            acc[j + 2] += ex * v.z;
            acc[j + 3] += ex * v.w;
        }
    }
    float inv = 1.f / (den + 1e-16f);
    float* dst = agg + (size_t)w * C + lane * EPL;
#pragma unroll
    for (int j = 0; j < EPL; j += 4) {
        float4 v;
        v.x = fmaxf(acc[j] * inv, 0.f);
        v.y = fmaxf(acc[j + 1] * inv, 0.f);
        v.z = fmaxf(acc[j + 2] * inv, 0.f);
        v.w = fmaxf(acc[j + 3] * inv, 0.f);
        *(float4*)(dst + j) = v;
    }
}

// ---------------- small kernels ----------------
__global__ void semantic_weights_kernel(const float* __restrict__ colsum,
                                        const float* __restrict__ q,
                                        int C, float invn, float* __restrict__ w) {
    __shared__ float sh0[256], sh1[256];
    int t = threadIdx.x;
    float s0 = 0.f, s1 = 0.f;
    for (int c = t; c < C; c += blockDim.x) {
        float qc = q[c];
        s0 += qc * colsum[c];
        s1 += qc * colsum[C + c];
    }
    sh0[t] = s0; sh1[t] = s1;
    __syncthreads();
    for (int o = blockDim.x / 2; o > 0; o >>= 1) {
        if (t < o) { sh0[t] += sh0[t + o]; sh1[t] += sh1[t + o]; }
        __syncthreads();
    }
    if (t == 0) {
        float a = sh0[0] * invn, b = sh1[0] * invn;
        float m = fmaxf(a, b);
        float ea = expf(a - m), eb = expf(b - m);
        float inv = 1.f / (ea + eb);
        w[0] = ea * inv; w[1] = eb * inv;
    }
}

// merged output: warps [0,NN) -> paper = l2n(w0*A + w1*B); [NN,2NN) -> author = l2n(Cc)
__global__ void l2norm_final_kernel(const float* __restrict__ A, const float* __restrict__ B,
                                    const float* __restrict__ Cc,
                                    const float* __restrict__ w, float* __restrict__ out) {
    int gw = (blockIdx.x * blockDim.x + threadIdx.x) >> 5;
    if (gw >= 2 * NN) return;
    int lane = threadIdx.x & 31;
    float4 v;
    if (gw < NN) {
        float w0 = w[0], w1 = w[1];
        float4 a = *(const float4*)(A + (size_t)gw * 128 + lane * 4);
        float4 b = *(const float4*)(B + (size_t)gw * 128 + lane * 4);
        v.x = w0 * a.x + w1 * b.x;
        v.y = w0 * a.y + w1 * b.y;
        v.z = w0 * a.z + w1 * b.z;
        v.w = w0 * a.w + w1 * b.w;
    } else {
        v = *(const float4*)(Cc + (size_t)(gw - NN) * 128 + lane * 4);
    }
    float s = v.x * v.x + v.y * v.y + v.z * v.z + v.w * v.w;
#pragma unroll
    for (int off = 16; off > 0; off >>= 1) s += __shfl_xor_sync(0xffffffffu, s, off);
    float inv = 1.f / fmaxf(sqrtf(s), 1e-12f);
    v.x *= inv; v.y *= inv; v.z *= inv; v.w *= inv;
    *(float4*)(out + (size_t)gw * 128 + lane * 4) = v;
}

// ---------------- host orchestration ----------------
enum {
    L_XP, L_XA, L_W0P, L_B0P, L_W0A, L_B0A,
    L_A0S_W, L_A0D_W, L_A0S_WB, L_A0D_WB, L_A0S_C, L_A0D_C,
    L_WK0, L_BK0, L_Q0,
    L_W1P, L_B1P, L_W1A, L_B1A,
    L_A1S_W, L_A1D_W, L_A1S_WB, L_A1D_WB, L_A1S_C, L_A1D_C,
    L_WK1, L_BK1, L_Q1, L_EIW, L_EIWB, L_EIC, L_COUNT
};

extern "C" void kernel_launch(void* const* d_in, const int* in_sizes, int n_in,
                              void* d_out, int out_size) {
    static const int mapSig[L_COUNT] = {
        0, 1, 2, 3, 4, 5, 6, 7, 8, 9, 10, 11, 12, 13, 14,
        15, 16, 17, 18, 19, 20, 21, 22, 23, 24, 25, 26, 27, 28, 29, 30};
    static const int mapDict[L_COUNT] = {
        0, 1, 5, 6, 7, 8, 9, 10, 11, 12, 13, 14, 15, 16, 17,
        18, 19, 20, 21, 22, 23, 24, 25, 26, 27, 28, 29, 30, 2, 3, 4};
    const int* mp = (n_in > 2 && in_sizes[2] == 2 * EE) ? mapDict : mapSig;

    const float* in_f[L_COUNT];
    for (int i = 0; i < L_COUNT; i++) in_f[i] = (const float*)d_in[mp[i]];
    const int* ei[3] = {(const int*)d_in[mp[L_EIW]],
                        (const int*)d_in[mp[L_EIWB]],
                        (const int*)d_in[mp[L_EIC]]};

    float *H0P, *H0A, *SC;
    float *AGG0a, *AGG0b, *AGG0c;
    float *H1P, *H1A, *AGG1a, *AGG1b, *AGG1c, *COLSUM, *W2, *BW;
    int *RP, *PERM, *CNT, *CUR, *BSUM;
    cudaGetSymbolAddress((void**)&H0P, g_H0P);
    cudaGetSymbolAddress((void**)&H0A, g_H0A);
    cudaGetSymbolAddress((void**)&SC, g_SC);
    cudaGetSymbolAddress((void**)&AGG0a, g_AGG0a);
    cudaGetSymbolAddress((void**)&AGG0b, g_AGG0b);
    cudaGetSymbolAddress((void**)&AGG0c, g_AGG0c);
    cudaGetSymbolAddress((void**)&H1P, g_H1P);
    cudaGetSymbolAddress((void**)&H1A, g_H1A);
    cudaGetSymbolAddress((void**)&AGG1a, g_AGG1a);
    cudaGetSymbolAddress((void**)&AGG1b, g_AGG1b);
    cudaGetSymbolAddress((void**)&AGG1c, g_AGG1c);
    cudaGetSymbolAddress((void**)&COLSUM, g_COLSUM);
    cudaGetSymbolAddress((void**)&W2, g_W2);
    cudaGetSymbolAddress((void**)&BW, g_BW);
    cudaGetSymbolAddress((void**)&RP, g_RP);
    cudaGetSymbolAddress((void**)&PERM, g_PERM);
    cudaGetSymbolAddress((void**)&CNT, g_CNT);
    cudaGetSymbolAddress((void**)&CUR, g_CUR);
    cudaGetSymbolAddress((void**)&BSUM, g_BSUM);

    float* S0 = SC + 0 * (NN * HEADS);
    float* S1 = SC + 1 * (NN * HEADS);
    float* S2 = SC + 2 * (NN * HEADS);
    float* S3 = SC + 3 * (NN * HEADS);
    float* S4 = SC + 4 * (NN * HEADS);
    float* S5 = SC + 5 * (NN * HEADS);
    float* W2a = W2;
    float* W2b = W2 + 2;
    const float* BW0P = BW + BW_W0P;
    const float* BW0A = BW + BW_W0A;
    const float* BWK0 = BW + BW_WK0;
    const float* BW1P = BW + BW_W1P;
    const float* BW1A = BW + BW_W1A;
    const float* BWK1 = BW + BW_WK1;

    cudaFuncSetAttribute(mma_gemm_big, cudaFuncAttributeMaxDynamicSharedMemorySize, GEMM_SMEM_BIG);

    const int TPB = 256;
    const int GY128 = (NN + 127) / 128;
    const int GY64 = (NN + 63) / 64;
    dim3 gProj0(2, GY128, 2);
    dim3 gProj1(1, GY64, 2);
    dim3 gCol256(2, GY64, 2);
    dim3 gCol128(1, GY64, 2);
    int warpBlocks = (NN * 32 + TPB - 1) / TPB;
    int scores6Blocks = (2 * NN + 7) / 8;

    // ======== CSR prefix (+weight preround) + L0 projections ========
    cudaMemsetAsync(CNT, 0, NTOT * sizeof(int));
    hist3_preround_kernel<<<(3 * EE + BW_TOTAL + TPB - 1) / TPB, TPB>>>(
        ei[0], ei[1], ei[2], CNT,
        in_f[L_W0P], in_f[L_W0A], in_f[L_WK0], in_f[L_W1P], in_f[L_W1A], in_f[L_WK1], BW);
    scanA_kernel<<<NBLK3, SCAN_B>>>(CNT, RP, BSUM);
    scanB_kernel<<<1, SCAN_B>>>(BSUM, NBLK3);
    mma_gemm_big<<<gProj0, TPB, GEMM_SMEM_BIG>>>(NN, HID, IN_DIM,
        in_f[L_XP], BW0P, in_f[L_B0P], H0P,
        in_f[L_XA], BW0A, in_f[L_B0A], H0A);
    scanC_kernel<<<(NTOT + TPB - 1) / TPB, TPB>>>(RP, BSUM, CUR);
    fill3_kernel<<<(3 * EE + TPB - 1) / TPB, TPB>>>(ei[0], ei[1], ei[2], CUR, PERM);

    // ======== Layer 0 ========
    scores6<HID, HEADS><<<scores6Blocks, TPB>>>(H0P, H0A,
        in_f[L_A0D_W], in_f[L_A0S_WB], in_f[L_A0S_C], in_f[L_A0D_C],
        in_f[L_A0S_W], in_f[L_A0D_WB],
        S1, S2, S4, S5, S0, S3);

    csr_gather_fused<HID, HEADS><<<warpBlocks, TPB>>>(RP + 0 * NN, PERM, S0, S1, H0A, AGG0a);
    csr_gather_fused<HID, HEADS><<<warpBlocks, TPB>>>(RP + 1 * NN, PERM, S2, S3, H0P, AGG0b);
    csr_gather_fused<HID, HEADS><<<warpBlocks, TPB>>>(RP + 2 * NN, PERM, S4, S5, H0P, AGG0c);

    cudaMemsetAsync(COLSUM, 0, 2 * HID * sizeof(float));
    mma_gemm<1, 0, 0><<<gCol256, TPB>>>(NN, HID, HID,
        AGG0a, AGG0c, BWK0, in_f[L_BK0], COLSUM, nullptr,
        nullptr, nullptr, nullptr, nullptr);
    semantic_weights_kernel<<<1, 256>>>(COLSUM, in_f[L_Q0], HID, 1.f / NN, W2a);

    // ======== Layer 1 ========
    mma_gemm<0, 1, 1><<<gProj1, TPB>>>(NN, OUT_DIM, HID,
        AGG0a, AGG0c, BW1P, in_f[L_B1P], H1P, W2a,
        AGG0b, BW1A, in_f[L_B1A], H1A);

    scores6<OUT_DIM, 1><<<scores6Blocks, TPB>>>(H1P, H1A,
        in_f[L_A1D_W], in_f[L_A1S_WB], in_f[L_A1S_C], in_f[L_A1D_C],
        in_f[L_A1S_W], in_f[L_A1D_WB],
        S1, S2, S4, S5, S0, S3);

    csr_gather_fused<OUT_DIM, 1><<<warpBlocks, TPB>>>(RP + 0 * NN, PERM, S0, S1, H1A, AGG1a);
    csr_gather_fused<OUT_DIM, 1><<<warpBlocks, TPB>>>(RP + 1 * NN, PERM, S2, S3, H1P, AGG1b);
    csr_gather_fused<OUT_DIM, 1><<<warpBlocks, TPB>>>(RP + 2 * NN, PERM, S4, S5, H1P, AGG1c);

    cudaMemsetAsync(COLSUM, 0, 2 * OUT_DIM * sizeof(float));
    mma_gemm<1, 0, 0><<<gCol128, TPB>>>(NN, OUT_DIM, OUT_DIM,
        AGG1a, AGG1c, BWK1, in_f[L_BK1], COLSUM, nullptr,
        nullptr, nullptr, nullptr, nullptr);
    semantic_weights_kernel<<<1, 256>>>(COLSUM, in_f[L_Q1], OUT_DIM, 1.f / NN, W2b);

    // ======== merged output epilogue ========
    l2norm_final_kernel<<<(2 * NN + 7) / 8, TPB>>>(AGG1a, AGG1c, AGG1b, W2b, (float*)d_out);
}